// round 8
// baseline (speedup 1.0000x reference)
#include <cuda_runtime.h>
#include <cuda_bf16.h>
#include <cstdint>
#include <cstring>

// Problem: N=32768 points, K=8192 centers, D=32. fp32 in, labels-as-fp32 out.
#define DIMS      32
#define NPOINTS   32768
#define KCENT     8192
#define TILE_N    128
#define NTILES    (KCENT / TILE_N)   // 64
#define THREADS   256                // 8 warps x 32 points
#define GRID      128                // 128 * 256 = 32768
#define BPITCH    80                 // bf16 B tile pitch (16B-aligned, conflict-free ldmatrix)
#define XPITCHB   144                // x smem pitch BYTES (16-aligned for cp.async!)
#define XPITCHW   36                 // x smem pitch in words
#define MARGIN    2.0f

// smem layout (bytes) — every cp.async dst offset divisible by 16
#define SM_B(s)    ((s) * (TILE_N * BPITCH))          // 2 x 10240
#define SM_C(s)    (20480 + (s) * (TILE_N * 128))     // fp32 centers, 2 x 16384
#define SM_C2(s)   (53248 + (s) * 512)                // ||c||^2, 2 x 512
#define SM_X       54272                              // 256 x 144 = 36864
#define SM_X2      91136                              // 256 x 4
#define SMEM_TOTAL 92160

// ---- precomputed bf16 screen operand + ||c||^2 ----
__device__ __align__(16) uint8_t g_bbf[(size_t)KCENT * 64];   // 512 KB: bf16(c)
__device__ float g_c2[KCENT];

__device__ __forceinline__ uint32_t pack_bf2(float lo, float hi) {
    __nv_bfloat162 h = __floats2bfloat162_rn(lo, hi);
    uint32_t u; memcpy(&u, &h, 4); return u;
}

// ---- prep: bf16 centers + exact ||c||^2 ----
__global__ void prep_centers(const float* __restrict__ c, int K) {
    int k = blockIdx.x * blockDim.x + threadIdx.x;
    if (k >= K) return;
    const float* row = c + (size_t)k * DIMS;
    float c2 = 0.0f;
    uint32_t w[16];
#pragma unroll
    for (int j = 0; j < 16; j++) {
        float a = row[2*j], b = row[2*j+1];
        w[j] = pack_bf2(a, b);
        c2 = fmaf(a, a, c2);
        c2 = fmaf(b, b, c2);
    }
    uint4* dst = reinterpret_cast<uint4*>(g_bbf + (size_t)k * 64);
#pragma unroll
    for (int i = 0; i < 4; i++)
        dst[i] = make_uint4(w[4*i], w[4*i+1], w[4*i+2], w[4*i+3]);
    g_c2[k] = c2;
}

// ---- ptx helpers ----
__device__ __forceinline__ uint32_t smem_u32(const void* p) {
    uint32_t a;
    asm("{ .reg .u64 t; cvta.to.shared.u64 t, %1; cvt.u32.u64 %0, t; }" : "=r"(a) : "l"(p));
    return a;
}
__device__ __forceinline__ void cp16(uint32_t dst, const void* src) {
    asm volatile("cp.async.cg.shared.global [%0], [%1], 16;" :: "r"(dst), "l"(src) : "memory");
}
#define MMA16816(d0,d1,d2,d3,a0,a1,a2,a3,b0,b1) \
    asm volatile("mma.sync.aligned.m16n8k16.row.col.f32.bf16.bf16.f32 " \
                 "{%0,%1,%2,%3}, {%4,%5,%6,%7}, {%8,%9}, {%0,%1,%2,%3};" \
                 : "+f"(d0), "+f"(d1), "+f"(d2), "+f"(d3) \
                 : "r"(a0), "r"(a1), "r"(a2), "r"(a3), "r"(b0), "r"(b1))

// ---- exact fp32 rescoring (rare path; outlined to protect I-cache) ----
__device__ __noinline__ float refine_d2(const float* __restrict__ xr,
                                        const float* __restrict__ cr,
                                        float x2v, float c2v) {
    float xc = 0.0f;
#pragma unroll
    for (int d = 0; d < DIMS; d++) xc = fmaf(xr[d], cr[d], xc);
    return fmaf(-2.0f, xc, x2v) + c2v;   // matches verified-flip-free form
}

// ---- main: bf16 screen GEMM + online exact refine + argmin ----
__global__ __launch_bounds__(THREADS, 1)
void tc_label(float* __restrict__ out, const float* __restrict__ xg,
              const float* __restrict__ cg) {
    extern __shared__ uint8_t smem[];
    const uint32_t sb = smem_u32(smem);
    const int tid = threadIdx.x, lane = tid & 31, warp = tid >> 5;
    const int lm4 = lane & 3, r = lane >> 2;
    const int cta = blockIdx.x;
    const int pbase = cta * 256 + warp * 32;

    float* sxf = reinterpret_cast<float*>(smem + SM_X);
    float* sx2 = reinterpret_cast<float*>(smem + SM_X2);

    // stage x fp32 (group 0): 256 rows x 8 x 16B, pitch 144 (16B-aligned)
    for (int i = tid; i < 256 * 8; i += THREADS) {
        int row = i >> 3, ch = i & 7;
        cp16(sb + SM_X + row * XPITCHB + ch * 16,
             xg + (size_t)(cta * 256 + row) * DIMS + ch * 4);
    }
    asm volatile("cp.async.commit_group;" ::: "memory");

    // B-tile loader: bf16 tile (512 chunks) + fp32 tile (1024) + c2 (32)
    auto issue = [&](int t) {
        const int s = t & 1;
        for (int i = tid; i < 1568; i += THREADS) {
            if (i < 512) {
                int row = i >> 2, ch = i & 3;
                cp16(sb + SM_B(s) + row * BPITCH + ch * 16,
                     g_bbf + (size_t)(t * TILE_N + row) * 64 + ch * 16);
            } else if (i < 1536) {
                int j = i - 512, row = j >> 3, ch = j & 7;
                cp16(sb + SM_C(s) + row * 128 + ch * 16,
                     cg + (size_t)(t * TILE_N + row) * DIMS + ch * 4);
            } else {
                int j = i - 1536;
                cp16(sb + SM_C2(s) + j * 16,
                     reinterpret_cast<const uint8_t*>(g_c2) + t * 512 + j * 16);
            }
        }
        asm volatile("cp.async.commit_group;" ::: "memory");
    };
    issue(0);
    issue(1);

    // x staged -> build A frags + x2
    asm volatile("cp.async.wait_group 2;" ::: "memory");
    __syncthreads();

    uint32_t A0[2][4], A1[2][4];
    {
        const float* x0 = sxf + (warp * 32 + r)      * XPITCHW;
        const float* x1 = sxf + (warp * 32 + r + 8)  * XPITCHW;
        const float* x2p = sxf + (warp * 32 + r + 16) * XPITCHW;
        const float* x3 = sxf + (warp * 32 + r + 24) * XPITCHW;
#pragma unroll
        for (int s = 0; s < 2; s++) {
            const int ka = 16 * s + 2 * lm4, kb2 = ka + 8;
            A0[s][0] = pack_bf2(x0[ka], x0[ka+1]);    A0[s][1] = pack_bf2(x1[ka], x1[ka+1]);
            A0[s][2] = pack_bf2(x0[kb2], x0[kb2+1]);  A0[s][3] = pack_bf2(x1[kb2], x1[kb2+1]);
            A1[s][0] = pack_bf2(x2p[ka], x2p[ka+1]);  A1[s][1] = pack_bf2(x3[ka], x3[ka+1]);
            A1[s][2] = pack_bf2(x2p[kb2], x2p[kb2+1]);A1[s][3] = pack_bf2(x3[kb2], x3[kb2+1]);
        }
    }
    {   // x2 for local row = tid
        const float* xr = sxf + tid * XPITCHW;
        float s = 0.0f;
#pragma unroll
        for (int d = 0; d < DIMS; d++) s = fmaf(xr[d], xr[d], s);
        sx2[tid] = s;
    }

    const float FLTMAX = 3.402823466e38f;
    float tmin[4] = { FLTMAX, FLTMAX, FLTMAX, FLTMAX };  // approx running min per row-group
    float bex[4]  = { FLTMAX, FLTMAX, FLTMAX, FLTMAX };  // exact best per row-group
    int   bidx[4] = { 0, 0, 0, 0 };

    const uint32_t lmoff = (uint32_t)(lane & 7) * BPITCH + (uint32_t)(lane >> 3) * 16;

    for (int t = 0; t < NTILES; t++) {
        if (t < NTILES - 1) asm volatile("cp.async.wait_group 1;" ::: "memory");
        else                asm volatile("cp.async.wait_group 0;" ::: "memory");
        __syncthreads();

        const int s = t & 1;
        const uint32_t bufB = sb + SM_B(s);
        const float* c2s = reinterpret_cast<const float*>(smem + SM_C2(s));
        const float* ctile = reinterpret_cast<const float*>(smem + SM_C(s));
        const int kb = t * TILE_N;

#pragma unroll 2
        for (int blk = 0; blk < TILE_N / 8; blk++) {
            const uint32_t ba = bufB + (uint32_t)blk * (8 * BPITCH) + lmoff;
            uint32_t b0, b1, b2, b3;
            asm volatile("ldmatrix.sync.aligned.m8n8.x4.shared.b16 {%0,%1,%2,%3}, [%4];"
                         : "=r"(b0), "=r"(b1), "=r"(b2), "=r"(b3) : "r"(ba));
            float acc0[4] = {0,0,0,0}, acc1[4] = {0,0,0,0};
            MMA16816(acc0[0], acc0[1], acc0[2], acc0[3], A0[0][0], A0[0][1], A0[0][2], A0[0][3], b0, b1);
            MMA16816(acc1[0], acc1[1], acc1[2], acc1[3], A1[0][0], A1[0][1], A1[0][2], A1[0][3], b0, b1);
            MMA16816(acc0[0], acc0[1], acc0[2], acc0[3], A0[1][0], A0[1][1], A0[1][2], A0[1][3], b2, b3);
            MMA16816(acc1[0], acc1[1], acc1[2], acc1[3], A1[1][0], A1[1][1], A1[1][2], A1[1][3], b2, b3);

            const int ci = blk * 8 + 2 * lm4;
            const float c2a = c2s[ci], c2b = c2s[ci + 1];
            const int k0 = kb + ci;
            // approx scores: v = c2 - 2*dot_bf16  (x2 constant over k; dropped)
            float va[4], vb[4];
            va[0] = fmaf(-2.0f, acc0[0], c2a); vb[0] = fmaf(-2.0f, acc0[1], c2b);
            va[1] = fmaf(-2.0f, acc0[2], c2a); vb[1] = fmaf(-2.0f, acc0[3], c2b);
            va[2] = fmaf(-2.0f, acc1[0], c2a); vb[2] = fmaf(-2.0f, acc1[1], c2b);
            va[3] = fmaf(-2.0f, acc1[2], c2a); vb[3] = fmaf(-2.0f, acc1[3], c2b);

            bool any = false;
#pragma unroll
            for (int g = 0; g < 4; g++)
                any |= (va[g] < tmin[g] + MARGIN) | (vb[g] < tmin[g] + MARGIN);
            if (any) {
                const float* cra = ctile + ci * 32;
#pragma unroll
                for (int g = 0; g < 4; g++) {
                    const float th = tmin[g] + MARGIN;
                    const int lrow = warp * 32 + g * 8 + r;
                    if (va[g] < th) {
                        float d2 = refine_d2(sxf + lrow * XPITCHW, cra, sx2[lrow], c2a);
                        if (d2 < bex[g]) { bex[g] = d2; bidx[g] = k0; }
                    }
                    if (vb[g] < th) {
                        float d2 = refine_d2(sxf + lrow * XPITCHW, cra + 32, sx2[lrow], c2b);
                        if (d2 < bex[g]) { bex[g] = d2; bidx[g] = k0 + 1; }
                    }
                }
            }
#pragma unroll
            for (int g = 0; g < 4; g++)
                tmin[g] = fminf(tmin[g], fminf(va[g], vb[g]));
        }
        __syncthreads();
        if (t + 2 < NTILES) issue(t + 2);
    }

    // merge across the 4 threads sharing each row (ties -> lower index)
#pragma unroll
    for (int g = 0; g < 4; g++) {
#pragma unroll
        for (int off = 1; off < 4; off <<= 1) {
            float ov = __shfl_xor_sync(0xFFFFFFFFu, bex[g], off);
            int   oi = __shfl_xor_sync(0xFFFFFFFFu, bidx[g], off);
            if (ov < bex[g] || (ov == bex[g] && oi < bidx[g])) { bex[g] = ov; bidx[g] = oi; }
        }
    }
    if (lm4 == 0) {
#pragma unroll
        for (int g = 0; g < 4; g++)
            out[pbase + g * 8 + r] = (float)bidx[g];
    }
}

extern "C" void kernel_launch(void* const* d_in, const int* in_sizes, int n_in,
                              void* d_out, int out_size) {
    const float* x; const float* c; int nx, nc;
    if (in_sizes[0] >= in_sizes[1]) { x = (const float*)d_in[0]; nx = in_sizes[0];
                                      c = (const float*)d_in[1]; nc = in_sizes[1]; }
    else                            { x = (const float*)d_in[1]; nx = in_sizes[1];
                                      c = (const float*)d_in[0]; nc = in_sizes[0]; }
    float* out = (float*)d_out;
    int K = nc / DIMS;   // 8192

    prep_centers<<<(K + 127) / 128, 128>>>(c, K);

    cudaFuncSetAttribute(tc_label, cudaFuncAttributeMaxDynamicSharedMemorySize, SMEM_TOTAL);
    tc_label<<<GRID, THREADS, SMEM_TOTAL>>>(out, x, c);
}

// round 9
// speedup vs baseline: 1.1681x; 1.1681x over previous
#include <cuda_runtime.h>
#include <cuda_bf16.h>
#include <cstdint>
#include <cstring>

// Problem: N=32768 points, K=8192 centers, D=32. fp32 in, labels-as-fp32 out.
#define DIMS      32
#define NPOINTS   32768
#define KCENT     8192
#define TILE_N    128
#define NTILES    (KCENT / TILE_N)   // 64
#define THREADS   256                // 8 warps x 16 points = 128 points/CTA
#define GRID      256                // 256 * 128 = 32768 ; 2 CTAs/SM
#define BPITCH    80                 // bf16 B tile pitch (16B aligned, conflict-free ldmatrix)
#define XPITCHW   36                 // x smem pitch words (144B, 16B-aligned)
#define MARGIN    2.0f

// smem layout (bytes) — all cp.async dsts 16B-aligned
#define SM_B(s)    ((s) * (TILE_N * BPITCH))     // 2 x 10240
#define SM_C2(s)   (20480 + (s) * 512)           // 2 x 512
#define SM_X       21504                         // 128 x 144 = 18432
#define SM_X2      39936                         // 128 x 4
#define SMEM_TOTAL 40448                         // -> 2 CTAs/SM

// ---- precomputed bf16 screen operand + exact ||c||^2 ----
__device__ __align__(16) uint8_t g_bbf[(size_t)KCENT * 64];   // 512 KB
__device__ float g_c2[KCENT];

__device__ __forceinline__ uint32_t pack_bf2(float lo, float hi) {
    __nv_bfloat162 h = __floats2bfloat162_rn(lo, hi);
    uint32_t u; memcpy(&u, &h, 4); return u;
}

__global__ void prep_centers(const float* __restrict__ c, int K) {
    int k = blockIdx.x * blockDim.x + threadIdx.x;
    if (k >= K) return;
    const float* row = c + (size_t)k * DIMS;
    float c2 = 0.0f;
    uint32_t w[16];
#pragma unroll
    for (int j = 0; j < 16; j++) {
        float a = row[2*j], b = row[2*j+1];
        w[j] = pack_bf2(a, b);
        c2 = fmaf(a, a, c2);
        c2 = fmaf(b, b, c2);
    }
    uint4* dst = reinterpret_cast<uint4*>(g_bbf + (size_t)k * 64);
#pragma unroll
    for (int i = 0; i < 4; i++)
        dst[i] = make_uint4(w[4*i], w[4*i+1], w[4*i+2], w[4*i+3]);
    g_c2[k] = c2;
}

// ---- ptx helpers ----
__device__ __forceinline__ uint32_t smem_u32(const void* p) {
    uint32_t a;
    asm("{ .reg .u64 t; cvta.to.shared.u64 t, %1; cvt.u32.u64 %0, t; }" : "=r"(a) : "l"(p));
    return a;
}
__device__ __forceinline__ void cp16(uint32_t dst, const void* src) {
    asm volatile("cp.async.cg.shared.global [%0], [%1], 16;" :: "r"(dst), "l"(src) : "memory");
}
#define MMA16816(d0,d1,d2,d3,a0,a1,a2,a3,b0,b1) \
    asm volatile("mma.sync.aligned.m16n8k16.row.col.f32.bf16.bf16.f32 " \
                 "{%0,%1,%2,%3}, {%4,%5,%6,%7}, {%8,%9}, {%0,%1,%2,%3};" \
                 : "+f"(d0), "+f"(d1), "+f"(d2), "+f"(d3) \
                 : "r"(a0), "r"(a1), "r"(a2), "r"(a3), "r"(b0), "r"(b1))

// ---- exact rescoring (rare; outlined) ----
__device__ __noinline__ float refine_d2(const float* __restrict__ xr,
                                        const float* __restrict__ cg,
                                        int k, float x2v) {
    const float4* cr = reinterpret_cast<const float4*>(cg + (size_t)k * DIMS);
    float xc = 0.0f;
#pragma unroll
    for (int q = 0; q < DIMS / 4; q++) {
        float4 v = cr[q];
        xc = fmaf(xr[4*q+0], v.x, xc);
        xc = fmaf(xr[4*q+1], v.y, xc);
        xc = fmaf(xr[4*q+2], v.z, xc);
        xc = fmaf(xr[4*q+3], v.w, xc);
    }
    return fmaf(-2.0f, xc, x2v) + g_c2[k];   // verified flip-free form
}

// ---- main: bf16 screen GEMM + sub-tile batched min/scan + exact refine ----
__global__ __launch_bounds__(THREADS, 2)
void tc_label(float* __restrict__ out, const float* __restrict__ xg,
              const float* __restrict__ cg) {
    extern __shared__ uint8_t smem[];
    const uint32_t sb = smem_u32(smem);
    const int tid = threadIdx.x, lane = tid & 31, warp = tid >> 5;
    const int lm4 = lane & 3, r = lane >> 2;
    const int cta = blockIdx.x;
    const int pbase = cta * 128 + warp * 16;

    float* sxf = reinterpret_cast<float*>(smem + SM_X);
    float* sx2 = reinterpret_cast<float*>(smem + SM_X2);

    // stage x: 128 rows x 8 x 16B, pitch 144
    for (int i = tid; i < 128 * 8; i += THREADS) {
        int row = i >> 3, ch = i & 7;
        cp16(sb + SM_X + row * 144 + ch * 16,
             xg + (size_t)(cta * 128 + row) * DIMS + ch * 4);
    }
    asm volatile("cp.async.commit_group;" ::: "memory");

    // B-tile loader: bf16 (512 chunks) + c2 (32 chunks)
    auto issue = [&](int t) {
        const int s = t & 1;
        for (int i = tid; i < 544; i += THREADS) {
            if (i < 512) {
                int row = i >> 2, ch = i & 3;
                cp16(sb + SM_B(s) + row * BPITCH + ch * 16,
                     g_bbf + (size_t)(t * TILE_N + row) * 64 + ch * 16);
            } else {
                int j = i - 512;
                cp16(sb + SM_C2(s) + j * 16,
                     reinterpret_cast<const uint8_t*>(g_c2) + t * 512 + j * 16);
            }
        }
        asm volatile("cp.async.commit_group;" ::: "memory");
    };
    issue(0);
    issue(1);

    asm volatile("cp.async.wait_group 2;" ::: "memory");
    __syncthreads();

    // A frags (16 points/warp, 2 ksteps) + x2
    uint32_t A[2][4];
    {
        const float* x0 = sxf + (warp * 16 + r) * XPITCHW;
        const float* x1 = x0 + 8 * XPITCHW;
#pragma unroll
        for (int s = 0; s < 2; s++) {
            const int ka = 16 * s + 2 * lm4, kb2 = ka + 8;
            A[s][0] = pack_bf2(x0[ka], x0[ka+1]);
            A[s][1] = pack_bf2(x1[ka], x1[ka+1]);
            A[s][2] = pack_bf2(x0[kb2], x0[kb2+1]);
            A[s][3] = pack_bf2(x1[kb2], x1[kb2+1]);
        }
    }
    if (tid < 128) {
        const float* xr = sxf + tid * XPITCHW;
        float s = 0.0f;
#pragma unroll
        for (int d = 0; d < DIMS; d++) s = fmaf(xr[d], xr[d], s);
        sx2[tid] = s;
    }
    // barrier below (loop head) orders sx2 before any refine read

    const float FLTMAX = 3.402823466e38f;
    float tmin0 = FLTMAX, tmin1 = FLTMAX;      // per-thread subset mins (g0 rows r, g1 rows r+8)
    float bex0 = FLTMAX, bex1 = FLTMAX;
    int   bi0 = 0, bi1 = 0;
    float x2v0 = 0.0f, x2v1 = 0.0f;            // loaded after first barrier
    const float* xr0 = sxf + (warp * 16 + r) * XPITCHW;
    const float* xr1 = xr0 + 8 * XPITCHW;
    bool x2init = false;

    const uint32_t lmoff = (uint32_t)(lane & 7) * BPITCH + (uint32_t)(lane >> 3) * 16;

    for (int t = 0; t < NTILES; t++) {
        if (t < NTILES - 1) asm volatile("cp.async.wait_group 1;" ::: "memory");
        else                asm volatile("cp.async.wait_group 0;" ::: "memory");
        __syncthreads();
        if (!x2init) {  // first pass: x2 now visible
            x2v0 = sx2[warp * 16 + r];
            x2v1 = sx2[warp * 16 + r + 8];
            x2init = true;
        }

        const int s = t & 1;
        const uint32_t bufB = sb + SM_B(s);
        const float* c2s = reinterpret_cast<const float*>(smem + SM_C2(s));
        const int kb = t * TILE_N;

#pragma unroll
        for (int sub = 0; sub < 2; sub++) {
            float v[8][4];
            // 8 blocks of 8 centers: GEMM + score
#pragma unroll
            for (int blk = 0; blk < 8; blk++) {
                const int gblk = sub * 8 + blk;
                const uint32_t ba = bufB + (uint32_t)gblk * (8 * BPITCH) + lmoff;
                uint32_t b0, b1, b2, b3;
                asm volatile("ldmatrix.sync.aligned.m8n8.x4.shared.b16 {%0,%1,%2,%3}, [%4];"
                             : "=r"(b0), "=r"(b1), "=r"(b2), "=r"(b3) : "r"(ba));
                float d0 = 0.f, d1 = 0.f, d2 = 0.f, d3 = 0.f;
                MMA16816(d0, d1, d2, d3, A[0][0], A[0][1], A[0][2], A[0][3], b0, b1);
                MMA16816(d0, d1, d2, d3, A[1][0], A[1][1], A[1][2], A[1][3], b2, b3);
                const int ci = gblk * 8 + 2 * lm4;
                const float c2a = c2s[ci], c2b = c2s[ci + 1];
                v[blk][0] = fmaf(-2.0f, d0, c2a);
                v[blk][1] = fmaf(-2.0f, d1, c2b);
                v[blk][2] = fmaf(-2.0f, d2, c2a);
                v[blk][3] = fmaf(-2.0f, d3, c2b);
            }
            // group mins (trees)
            float p0[8], p1[8];
#pragma unroll
            for (int b = 0; b < 8; b++) {
                p0[b] = fminf(v[b][0], v[b][1]);
                p1[b] = fminf(v[b][2], v[b][3]);
            }
            float m0 = fminf(fminf(fminf(p0[0], p0[1]), fminf(p0[2], p0[3])),
                             fminf(fminf(p0[4], p0[5]), fminf(p0[6], p0[7])));
            float m1 = fminf(fminf(fminf(p1[0], p1[1]), fminf(p1[2], p1[3])),
                             fminf(fminf(p1[4], p1[5]), fminf(p1[6], p1[7])));

            // rare: scan + exact refine
            if (m0 < tmin0 + MARGIN || m1 < tmin1 + MARGIN) {
                const float thr0 = fminf(tmin0, m0) + MARGIN;
                const float thr1 = fminf(tmin1, m1) + MARGIN;
                const int k00 = kb + sub * 64 + 2 * lm4;
#pragma unroll
                for (int blk = 0; blk < 8; blk++) {
                    const int kk = k00 + blk * 8;
                    if (v[blk][0] < thr0) {
                        float d2 = refine_d2(xr0, cg, kk, x2v0);
                        if (d2 < bex0) { bex0 = d2; bi0 = kk; }
                    }
                    if (v[blk][1] < thr0) {
                        float d2 = refine_d2(xr0, cg, kk + 1, x2v0);
                        if (d2 < bex0) { bex0 = d2; bi0 = kk + 1; }
                    }
                    if (v[blk][2] < thr1) {
                        float d2 = refine_d2(xr1, cg, kk, x2v1);
                        if (d2 < bex1) { bex1 = d2; bi1 = kk; }
                    }
                    if (v[blk][3] < thr1) {
                        float d2 = refine_d2(xr1, cg, kk + 1, x2v1);
                        if (d2 < bex1) { bex1 = d2; bi1 = kk + 1; }
                    }
                }
            }
            tmin0 = fminf(tmin0, m0);
            tmin1 = fminf(tmin1, m1);
        }
        __syncthreads();
        if (t + 2 < NTILES) issue(t + 2);
    }

    // merge across the 4 threads sharing each row (ties -> lower index)
#pragma unroll
    for (int off = 1; off < 4; off <<= 1) {
        float ov = __shfl_xor_sync(0xFFFFFFFFu, bex0, off);
        int   oi = __shfl_xor_sync(0xFFFFFFFFu, bi0, off);
        if (ov < bex0 || (ov == bex0 && oi < bi0)) { bex0 = ov; bi0 = oi; }
        ov = __shfl_xor_sync(0xFFFFFFFFu, bex1, off);
        oi = __shfl_xor_sync(0xFFFFFFFFu, bi1, off);
        if (ov < bex1 || (ov == bex1 && oi < bi1)) { bex1 = ov; bi1 = oi; }
    }
    if (lm4 == 0) {
        out[pbase + r]     = (float)bi0;
        out[pbase + r + 8] = (float)bi1;
    }
}

extern "C" void kernel_launch(void* const* d_in, const int* in_sizes, int n_in,
                              void* d_out, int out_size) {
    const float* x; const float* c; int nx, nc;
    if (in_sizes[0] >= in_sizes[1]) { x = (const float*)d_in[0]; nx = in_sizes[0];
                                      c = (const float*)d_in[1]; nc = in_sizes[1]; }
    else                            { x = (const float*)d_in[1]; nx = in_sizes[1];
                                      c = (const float*)d_in[0]; nc = in_sizes[0]; }
    float* out = (float*)d_out;
    int K = nc / DIMS;   // 8192

    prep_centers<<<(K + 127) / 128, 128>>>(c, K);

    cudaFuncSetAttribute(tc_label, cudaFuncAttributeMaxDynamicSharedMemorySize, SMEM_TOTAL);
    tc_label<<<GRID, THREADS, SMEM_TOTAL>>>(out, x, c);
}

// round 10
// speedup vs baseline: 2.1374x; 1.8299x over previous
#include <cuda_runtime.h>
#include <cuda_bf16.h>
#include <cstdint>
#include <cstring>

// Problem: N=32768 points, K=8192 centers, D=32. fp32 in, labels-as-fp32 out.
#define DIMS      32
#define KCENT     8192
#define TILE_N    128
#define NTILES    (KCENT / TILE_N)   // 64
#define THREADS   256                // 8 warps x 16 points = 128 points/CTA
#define GRID      256                // 256*128 = 32768 ; 2 CTAs/SM
#define BPITCH    80
#define XPITCHW   36                 // x smem pitch words (144B)
#define MARGIN    1.25f
#define CAP       8192               // candidate list entries per CTA

// smem layout (bytes), all cp.async dsts 16B-aligned
#define SM_B(s)    ((s) * (TILE_N * BPITCH))     // 2 x 10240
#define SM_C2(s)   (20480 + (s) * 512)
#define SM_X       21504                         // 128*144 = 18432
#define SM_X2      39936                         // 512
#define SM_BEST    40448                         // 128 * 8 = 1024
#define SM_CNT     41472                         // 16
#define SM_LIST    41488                         // 8192*4 = 32768
#define SMEM_TOTAL 74256

__device__ __align__(16) uint8_t g_bbf[(size_t)KCENT * 64];
__device__ float g_c2[KCENT];

__device__ __forceinline__ uint32_t pack_bf2(float lo, float hi) {
    __nv_bfloat162 h = __floats2bfloat162_rn(lo, hi);
    uint32_t u; memcpy(&u, &h, 4); return u;
}

__global__ void prep_centers(const float* __restrict__ c, int K) {
    int k = blockIdx.x * blockDim.x + threadIdx.x;
    if (k >= K) return;
    const float* row = c + (size_t)k * DIMS;
    float c2 = 0.0f;
    uint32_t w[16];
#pragma unroll
    for (int j = 0; j < 16; j++) {
        float a = row[2*j], b = row[2*j+1];
        w[j] = pack_bf2(a, b);
        c2 = fmaf(a, a, c2);
        c2 = fmaf(b, b, c2);
    }
    uint4* dst = reinterpret_cast<uint4*>(g_bbf + (size_t)k * 64);
#pragma unroll
    for (int i = 0; i < 4; i++)
        dst[i] = make_uint4(w[4*i], w[4*i+1], w[4*i+2], w[4*i+3]);
    g_c2[k] = c2;
}

__device__ __forceinline__ uint32_t smem_u32(const void* p) {
    uint32_t a;
    asm("{ .reg .u64 t; cvta.to.shared.u64 t, %1; cvt.u32.u64 %0, t; }" : "=r"(a) : "l"(p));
    return a;
}
__device__ __forceinline__ void cp16(uint32_t dst, const void* src) {
    asm volatile("cp.async.cg.shared.global [%0], [%1], 16;" :: "r"(dst), "l"(src) : "memory");
}
#define MMA16816(d0,d1,d2,d3,a0,a1,a2,a3,b0,b1) \
    asm volatile("mma.sync.aligned.m16n8k16.row.col.f32.bf16.bf16.f32 " \
                 "{%0,%1,%2,%3}, {%4,%5,%6,%7}, {%8,%9}, {%0,%1,%2,%3};" \
                 : "+f"(d0), "+f"(d1), "+f"(d2), "+f"(d3) \
                 : "r"(a0), "r"(a1), "r"(a2), "r"(a3), "r"(b0), "r"(b1))

__global__ __launch_bounds__(THREADS, 2)
void tc_label(float* __restrict__ out, const float* __restrict__ xg,
              const float* __restrict__ cg) {
    extern __shared__ uint8_t smem[];
    const uint32_t sb = smem_u32(smem);
    const int tid = threadIdx.x, lane = tid & 31, warp = tid >> 5;
    const int lm4 = lane & 3, r = lane >> 2;
    const int cta = blockIdx.x;

    float* sxf = reinterpret_cast<float*>(smem + SM_X);
    float* sx2 = reinterpret_cast<float*>(smem + SM_X2);
    unsigned long long* best = reinterpret_cast<unsigned long long*>(smem + SM_BEST);
    int* lcnt = reinterpret_cast<int*>(smem + SM_CNT);
    uint32_t* list = reinterpret_cast<uint32_t*>(smem + SM_LIST);

    if (tid < 128) best[tid] = 0xFFFFFFFFFFFFFFFFull;
    if (tid == 0) *lcnt = 0;

    // stage x: 128 rows x 8 x 16B, pitch 144
    for (int i = tid; i < 128 * 8; i += THREADS) {
        int row = i >> 3, ch = i & 7;
        cp16(sb + SM_X + row * 144 + ch * 16,
             xg + (size_t)(cta * 128 + row) * DIMS + ch * 4);
    }
    asm volatile("cp.async.commit_group;" ::: "memory");

    auto issue = [&](int t) {
        const int s = t & 1;
        for (int i = tid; i < 544; i += THREADS) {
            if (i < 512) {
                int row = i >> 2, ch = i & 3;
                cp16(sb + SM_B(s) + row * BPITCH + ch * 16,
                     g_bbf + (size_t)(t * TILE_N + row) * 64 + ch * 16);
            } else {
                int j = i - 512;
                cp16(sb + SM_C2(s) + j * 16,
                     reinterpret_cast<const uint8_t*>(g_c2) + t * 512 + j * 16);
            }
        }
        asm volatile("cp.async.commit_group;" ::: "memory");
    };
    issue(0);
    issue(1);

    asm volatile("cp.async.wait_group 2;" ::: "memory");
    __syncthreads();

    // A frags + x2
    uint32_t A[2][4];
    {
        const float* x0 = sxf + (warp * 16 + r) * XPITCHW;
        const float* x1 = x0 + 8 * XPITCHW;
#pragma unroll
        for (int s = 0; s < 2; s++) {
            const int ka = 16 * s + 2 * lm4, kb2 = ka + 8;
            A[s][0] = pack_bf2(x0[ka], x0[ka+1]);
            A[s][1] = pack_bf2(x1[ka], x1[ka+1]);
            A[s][2] = pack_bf2(x0[kb2], x0[kb2+1]);
            A[s][3] = pack_bf2(x1[kb2], x1[kb2+1]);
        }
    }
    if (tid < 128) {
        const float* xr = sxf + tid * XPITCHW;
        float s = 0.0f;
#pragma unroll
        for (int d = 0; d < DIMS; d++) s = fmaf(xr[d], xr[d], s);
        sx2[tid] = s;
    }

    const uint32_t lmoff = (uint32_t)(lane & 7) * BPITCH + (uint32_t)(lane >> 3) * 16;
    const int rowA = warp * 16 + r, rowB = rowA + 8;
    float thr0 = 3.402823466e38f, thr1 = 3.402823466e38f;

    // ---- tile-0 min-only prepass (warms thresholds; kills push storms) ----
    asm volatile("cp.async.wait_group 1;" ::: "memory");
    __syncthreads();
    {
        const uint32_t bufB = sb + SM_B(0);
        const float* c2s = reinterpret_cast<const float*>(smem + SM_C2(0));
#pragma unroll 4
        for (int gblk = 0; gblk < 16; gblk++) {
            const uint32_t ba = bufB + (uint32_t)gblk * (8 * BPITCH) + lmoff;
            uint32_t b0, b1, b2, b3;
            asm volatile("ldmatrix.sync.aligned.m8n8.x4.shared.b16 {%0,%1,%2,%3}, [%4];"
                         : "=r"(b0), "=r"(b1), "=r"(b2), "=r"(b3) : "r"(ba));
            float d0 = 0.f, d1 = 0.f, d2 = 0.f, d3 = 0.f;
            MMA16816(d0, d1, d2, d3, A[0][0], A[0][1], A[0][2], A[0][3], b0, b1);
            MMA16816(d0, d1, d2, d3, A[1][0], A[1][1], A[1][2], A[1][3], b2, b3);
            const int ci = gblk * 8 + 2 * lm4;
            float2 c2p = *reinterpret_cast<const float2*>(c2s + ci);
            float m0 = fminf(fmaf(-2.f, d0, c2p.x), fmaf(-2.f, d1, c2p.y));
            float m1 = fminf(fmaf(-2.f, d2, c2p.x), fmaf(-2.f, d3, c2p.y));
            thr0 = fminf(thr0, m0 + MARGIN);
            thr1 = fminf(thr1, m1 + MARGIN);
        }
        // quad exchange (lanes sharing a row)
        thr0 = fminf(thr0, __shfl_xor_sync(~0u, thr0, 1));
        thr0 = fminf(thr0, __shfl_xor_sync(~0u, thr0, 2));
        thr1 = fminf(thr1, __shfl_xor_sync(~0u, thr1, 1));
        thr1 = fminf(thr1, __shfl_xor_sync(~0u, thr1, 2));
    }

    // ---- main screen loop with candidate pushes ----
    for (int t = 0; t < NTILES; t++) {
        if (t < NTILES - 1) asm volatile("cp.async.wait_group 1;" ::: "memory");
        else                asm volatile("cp.async.wait_group 0;" ::: "memory");
        __syncthreads();

        const int s = t & 1;
        const uint32_t bufB = sb + SM_B(s);
        const float* c2s = reinterpret_cast<const float*>(smem + SM_C2(s));
        const int kb = t * TILE_N;

#pragma unroll 4
        for (int gblk = 0; gblk < 16; gblk++) {
            const uint32_t ba = bufB + (uint32_t)gblk * (8 * BPITCH) + lmoff;
            uint32_t b0, b1, b2, b3;
            asm volatile("ldmatrix.sync.aligned.m8n8.x4.shared.b16 {%0,%1,%2,%3}, [%4];"
                         : "=r"(b0), "=r"(b1), "=r"(b2), "=r"(b3) : "r"(ba));
            float d0 = 0.f, d1 = 0.f, d2 = 0.f, d3 = 0.f;
            MMA16816(d0, d1, d2, d3, A[0][0], A[0][1], A[0][2], A[0][3], b0, b1);
            MMA16816(d0, d1, d2, d3, A[1][0], A[1][1], A[1][2], A[1][3], b2, b3);
            const int ci = gblk * 8 + 2 * lm4;
            float2 c2p = *reinterpret_cast<const float2*>(c2s + ci);
            float v0 = fmaf(-2.f, d0, c2p.x), v1 = fmaf(-2.f, d1, c2p.y);
            float v2 = fmaf(-2.f, d2, c2p.x), v3 = fmaf(-2.f, d3, c2p.y);
            float m0 = fminf(v0, v1), m1 = fminf(v2, v3);

            unsigned bal = __ballot_sync(~0u, (m0 < thr0) | (m1 < thr1));
            if (bal) {   // warp-uniform rare path: push candidates
                bool p0 = v0 < thr0, p1 = v1 < thr0;
                bool p2 = v2 < thr1, p3 = v3 < thr1;
                int n = (int)p0 + (int)p1 + (int)p2 + (int)p3;
                int sc = n;
#pragma unroll
                for (int o = 1; o < 32; o <<= 1) {
                    int tv = __shfl_up_sync(~0u, sc, o);
                    if (lane >= o) sc += tv;
                }
                int total = __shfl_sync(~0u, sc, 31);
                int base0 = 0;
                if (lane == 31) base0 = atomicAdd(lcnt, total);
                base0 = __shfl_sync(~0u, base0, 31);
                int pos = base0 + sc - n;
                const int k0 = kb + ci;
                if (p0) { if (pos < CAP) list[pos] = ((uint32_t)rowA << 13) | k0;       pos++; }
                if (p1) { if (pos < CAP) list[pos] = ((uint32_t)rowA << 13) | (k0 + 1); pos++; }
                if (p2) { if (pos < CAP) list[pos] = ((uint32_t)rowB << 13) | k0;       pos++; }
                if (p3) { if (pos < CAP) list[pos] = ((uint32_t)rowB << 13) | (k0 + 1); pos++; }
            }
            thr0 = fminf(thr0, m0 + MARGIN);
            thr1 = fminf(thr1, m1 + MARGIN);
        }
        // tighten thresholds across the quad each tile
        thr0 = fminf(thr0, __shfl_xor_sync(~0u, thr0, 1));
        thr0 = fminf(thr0, __shfl_xor_sync(~0u, thr0, 2));
        thr1 = fminf(thr1, __shfl_xor_sync(~0u, thr1, 1));
        thr1 = fminf(thr1, __shfl_xor_sync(~0u, thr1, 2));

        __syncthreads();
        if (t + 2 < NTILES) issue(t + 2);
    }

    // ---- cooperative exact refine: one candidate per quad ----
    __syncthreads();
    const int cnt = min(*lcnt, CAP);
    const int qid = lane >> 2, ql = lane & 3;
    for (int i0 = warp * 8; i0 < cnt; i0 += 64) {
        const int i = i0 + qid;
        const bool act = (i < cnt);
        const uint32_t e = act ? list[i] : 0u;
        const int row = e >> 13, k = e & 8191;
        const float4* cr = reinterpret_cast<const float4*>(cg + (size_t)k * DIMS);
        const float4* xr = reinterpret_cast<const float4*>(sxf + row * XPITCHW);
        float4 ca = cr[2*ql], cb = cr[2*ql+1];
        float4 xa = xr[2*ql], xb = xr[2*ql+1];
        float p = ca.x * xa.x;
        p = fmaf(ca.y, xa.y, p); p = fmaf(ca.z, xa.z, p); p = fmaf(ca.w, xa.w, p);
        p = fmaf(cb.x, xb.x, p); p = fmaf(cb.y, xb.y, p);
        p = fmaf(cb.z, xb.z, p); p = fmaf(cb.w, xb.w, p);
        p += __shfl_xor_sync(~0u, p, 1);
        p += __shfl_xor_sync(~0u, p, 2);
        if (act && ql == 0) {
            float d2 = fmaf(-2.f, p, sx2[row]) + g_c2[k];
            d2 = fmaxf(d2, 0.0f);   // keep float-bits ordering monotonic
            unsigned long long key =
                ((unsigned long long)__float_as_uint(d2) << 32) | (unsigned)k;
            atomicMin(best + row, key);   // exact d2 order; lower k wins ties
        }
    }
    __syncthreads();
    if (tid < 128)
        out[cta * 128 + tid] = (float)(unsigned)(best[tid] & 8191ull);
}

extern "C" void kernel_launch(void* const* d_in, const int* in_sizes, int n_in,
                              void* d_out, int out_size) {
    const float* x; const float* c; int nx, nc;
    if (in_sizes[0] >= in_sizes[1]) { x = (const float*)d_in[0]; nx = in_sizes[0];
                                      c = (const float*)d_in[1]; nc = in_sizes[1]; }
    else                            { x = (const float*)d_in[1]; nx = in_sizes[1];
                                      c = (const float*)d_in[0]; nc = in_sizes[0]; }
    float* out = (float*)d_out;
    int K = nc / DIMS;

    prep_centers<<<(K + 127) / 128, 128>>>(c, K);

    cudaFuncSetAttribute(tc_label, cudaFuncAttributeMaxDynamicSharedMemorySize, SMEM_TOTAL);
    tc_label<<<GRID, THREADS, SMEM_TOTAL>>>(out, x, c);
}